// round 16
// baseline (speedup 1.0000x reference)
#include <cuda_runtime.h>
#include <cuda_bf16.h>
#include <cstdint>

#define H   2048
#define I1  1024
#define I2  2048
#define E   32
#define MAXT 8192
#define MAXPAIR (2*MAXT)
#define MAXPAIRP (MAXPAIR + 128)
#define MAXTILES 160
#define TMM 128          // CTA M tile
#define TNN 64           // CTA N tile
#define NX  32           // N-chunks per layer (I2/64 == H/64 == 32)
#define KCB 128          // K chunk in bytes (=128 int8) per stage
#define A_T 16384        // 128x128B int8 A tile (i1 or i2)
#define B_T 8192         // 64x128B int8 B tile
#define STAGE_BYTES (2*A_T + 2*B_T)        /* 49152 */
#define NSTAGE 3
#define SMEM_DYN (NSTAGE*STAGE_BYTES)      /* 147456 */
#define PGRID 152        // persistent grid (GB300 = 152 SMs)

// ---------------- device scratch ----------------
__device__ uint4 g_xi1[(size_t)MAXPAIRP*(H/16)];
__device__ uint4 g_xi2[(size_t)MAXPAIRP*(H/16)];
__device__ uint4 g_w1i1[(size_t)E*I2*(H/16)];
__device__ uint4 g_w1i2[(size_t)E*I2*(H/16)];
__device__ uint4 g_w2i1[(size_t)E*H*(I1/16)];
__device__ uint4 g_w2i2[(size_t)E*H*(I1/16)];
__device__ uint4 g_hi1[(size_t)MAXPAIRP*(I1/16)];
__device__ uint4 g_hi2[(size_t)MAXPAIRP*(I1/16)];
__device__ float g_h[(size_t)MAXPAIRP*I1];
__device__ float g_xs[MAXPAIRP];
__device__ float g_hs[MAXPAIRP];
__device__ float g_w1s[E*I2];
__device__ float g_w2s[E*H];

__device__ float g_logits[MAXT * E];
__device__ int   g_counts[E];
__device__ int   g_cursor[E];
__device__ int   g_offsets[E];
__device__ int   g_tok_e[MAXT * 2];
__device__ float g_tok_g[MAXT * 2];
__device__ int   g_pair_tok[MAXPAIR];
__device__ float g_pair_gate[MAXPAIR];
__device__ int   g_tile_expert[MAXTILES];
__device__ int   g_tile_rowbase[MAXTILES];
__device__ int   g_tile_pairbase[MAXTILES];
__device__ int   g_n_tiles;

// ---------------- PTX helpers (plain-sm_103-legal) ----------------
__device__ __forceinline__ uint32_t smem_u32(const void* p) {
    uint32_t a;
    asm("{ .reg .u64 t; cvta.to.shared.u64 t, %1; cvt.u32.u64 %0, t; }" : "=r"(a) : "l"(p));
    return a;
}
__device__ __forceinline__ void cp16(uint32_t s, const void* g) {
    asm volatile("cp.async.cg.shared.global [%0], [%1], 16;" :: "r"(s), "l"(g));
}
#define CP_COMMIT() asm volatile("cp.async.commit_group;" ::: "memory")
#define CP_WAIT(n)  asm volatile("cp.async.wait_group %0;" :: "n"(n) : "memory")

__device__ __forceinline__ void ldm_x4(uint32_t r[4], uint32_t addr) {
    asm volatile("ldmatrix.sync.aligned.m8n8.x4.shared.b16 {%0,%1,%2,%3}, [%4];"
        : "=r"(r[0]), "=r"(r[1]), "=r"(r[2]), "=r"(r[3]) : "r"(addr));
}
__device__ __forceinline__ void mma_s8(int c[4], const uint32_t a[4],
                                       uint32_t b0, uint32_t b1) {
    asm volatile("mma.sync.aligned.m16n8k32.row.col.s32.s8.s8.s32 "
        "{%0,%1,%2,%3}, {%4,%5,%6,%7}, {%8,%9}, {%0,%1,%2,%3};"
        : "+r"(c[0]), "+r"(c[1]), "+r"(c[2]), "+r"(c[3])
        : "r"(a[0]), "r"(a[1]), "r"(a[2]), "r"(a[3]), "r"(b0), "r"(b1));
}
__device__ __forceinline__ uint32_t swz(uint32_t x) { return x ^ ((x >> 3) & 0x70); }

__device__ __forceinline__ float blockmax8(float v, float* sred) {
    int tid = threadIdx.x;
#pragma unroll
    for (int o = 16; o; o >>= 1) v = fmaxf(v, __shfl_xor_sync(0xffffffffu, v, o));
    if ((tid & 31) == 0) sred[tid >> 5] = v;
    __syncthreads();
    float m = sred[0];
#pragma unroll
    for (int i = 1; i < 8; i++) m = fmaxf(m, sred[i]);
    return m;
}
// quantize one value to (q1, q2): v ~= (s/127)*(q1 + q2/254)
__device__ __forceinline__ void quant2(float v, float inv, int& q1, int& q2) {
    float u = v * inv;
    float r = rintf(u);
    q1 = (int)r;
    q2 = (int)rintf((u - r) * 254.0f);
}

// ---------------- routing kernels ----------------
__global__ void init_kernel() {
    int i = threadIdx.x;
    if (i < E) { g_counts[i] = 0; g_cursor[i] = 0; }
    if (i == 0) g_n_tiles = 0;
}

__global__ __launch_bounds__(256) void router_gemm(const float* __restrict__ x,
                                                   const float* __restrict__ gw,
                                                   const float* __restrict__ gb) {
    __shared__ __align__(16) float xs[32][36];
    __shared__ __align__(16) float ws[32][36];
    int tid = threadIdx.x;
    int tx = tid & 7, ty = tid >> 3;
    int tbase = blockIdx.x * 32;
    int lrow = tid >> 3, lk4 = (tid & 7) * 4;
    float acc[4] = {0.f, 0.f, 0.f, 0.f};
    const float* xp = x  + (size_t)(tbase + lrow) * H + lk4;
    const float* wp = gw + (size_t)lrow * H + lk4;
    for (int kb = 0; kb < H; kb += 32) {
        float4 xv = *(const float4*)(xp + kb);
        float4 wv = *(const float4*)(wp + kb);
        *(float4*)&xs[lrow][lk4] = xv;
        ws[lk4+0][lrow] = wv.x; ws[lk4+1][lrow] = wv.y;
        ws[lk4+2][lrow] = wv.z; ws[lk4+3][lrow] = wv.w;
        __syncthreads();
#pragma unroll
        for (int k = 0; k < 32; ++k) {
            float xv1 = xs[ty][k];
            float4 w4 = *(const float4*)&ws[k][tx*4];
            acc[0] = fmaf(xv1, w4.x, acc[0]); acc[1] = fmaf(xv1, w4.y, acc[1]);
            acc[2] = fmaf(xv1, w4.z, acc[2]); acc[3] = fmaf(xv1, w4.w, acc[3]);
        }
        __syncthreads();
    }
    int t = tbase + ty;
#pragma unroll
    for (int j = 0; j < 4; ++j) g_logits[t*E + tx*4 + j] = acc[j] + gb[tx*4 + j];
}

__global__ void topk_kernel(int T) {
    int warp = (blockIdx.x * blockDim.x + threadIdx.x) >> 5;
    int lane = threadIdx.x & 31;
    if (warp >= T) return;
    float l = g_logits[warp * E + lane];
    float m = l;
#pragma unroll
    for (int o = 16; o; o >>= 1) m = fmaxf(m, __shfl_xor_sync(0xffffffffu, m, o));
    float p = __expf(l - m);
    float s = p;
#pragma unroll
    for (int o = 16; o; o >>= 1) s += __shfl_xor_sync(0xffffffffu, s, o);
    float prob = p / s;
    float v = prob; int idx = lane;
#pragma unroll
    for (int o = 16; o; o >>= 1) {
        float vo = __shfl_xor_sync(0xffffffffu, v, o);
        int   io = __shfl_xor_sync(0xffffffffu, idx, o);
        if (vo > v || (vo == v && io < idx)) { v = vo; idx = io; }
    }
    int e0 = idx; float g0 = v;
    float v2 = (lane == e0) ? -1.0f : prob; int idx2 = lane;
#pragma unroll
    for (int o = 16; o; o >>= 1) {
        float vo = __shfl_xor_sync(0xffffffffu, v2, o);
        int   io = __shfl_xor_sync(0xffffffffu, idx2, o);
        if (vo > v2 || (vo == v2 && io < idx2)) { v2 = vo; idx2 = io; }
    }
    if (lane == 0) {
        g_tok_e[warp*2+0] = e0;   g_tok_g[warp*2+0] = g0;
        g_tok_e[warp*2+1] = idx2; g_tok_g[warp*2+1] = v2;
        atomicAdd(&g_counts[e0], 1);
        atomicAdd(&g_counts[idx2], 1);
    }
}

__global__ void scan_kernel() {
    if (threadIdx.x != 0) return;
    int off = 0, nt = 0;
    for (int e = 0; e < E; ++e) {
        g_offsets[e] = off;
        int c = g_counts[e];
        for (int rb = 0; rb < c; rb += TMM) {
            g_tile_expert[nt] = e; g_tile_rowbase[nt] = rb; g_tile_pairbase[nt] = off + rb;
            nt++;
        }
        off += c;
    }
    g_n_tiles = nt;
}

__global__ void scatter_kernel(int T) {
    int t = blockIdx.x * blockDim.x + threadIdx.x;
    if (t >= T) return;
#pragma unroll
    for (int j = 0; j < 2; ++j) {
        int e = g_tok_e[t*2+j];
        int pos = g_offsets[e] + atomicAdd(&g_cursor[e], 1);
        g_pair_tok[pos]  = t;
        g_pair_gate[pos] = g_tok_g[t*2+j];
    }
}

// ---------------- quantization kernels (R10-proven) ----------------
__global__ __launch_bounds__(256) void quant_w1(const float* __restrict__ w1) {
    __shared__ float sred[8];
    int row = blockIdx.x;                       // 0 .. E*I2-1
    int tid = threadIdx.x;
    const float4* src = (const float4*)(w1 + (size_t)row * H);
    float4 a = src[tid*2], b = src[tid*2+1];
    float f[8] = {a.x,a.y,a.z,a.w,b.x,b.y,b.z,b.w};
    float mv = 0.f;
#pragma unroll
    for (int j = 0; j < 8; j++) mv = fmaxf(mv, fabsf(f[j]));
    float m = blockmax8(mv, sred);
    m = m > 0.f ? m : 1.0f;
    if (tid == 0) g_w1s[row] = m;
    float inv = 127.0f / m;
    uint32_t p1[2] = {0,0}, p2[2] = {0,0};
#pragma unroll
    for (int j = 0; j < 8; j++) {
        int q1, q2; quant2(f[j], inv, q1, q2);
        p1[j>>2] |= (uint32_t)(q1 & 255) << ((j&3)*8);
        p2[j>>2] |= (uint32_t)(q2 & 255) << ((j&3)*8);
    }
    ((uint2*)g_w1i1)[(size_t)row*(H/8) + tid] = make_uint2(p1[0], p1[1]);
    ((uint2*)g_w1i2)[(size_t)row*(H/8) + tid] = make_uint2(p2[0], p2[1]);
}

__global__ __launch_bounds__(256) void quant_w2(const float* __restrict__ w2) {
    __shared__ float sred[8];
    int row = blockIdx.x;                       // 0 .. E*H-1
    int tid = threadIdx.x;
    const float4* src = (const float4*)(w2 + (size_t)row * I1);
    float4 a = src[tid];
    float f[4] = {a.x,a.y,a.z,a.w};
    float mv = fmaxf(fmaxf(fabsf(f[0]), fabsf(f[1])), fmaxf(fabsf(f[2]), fabsf(f[3])));
    float m = blockmax8(mv, sred);
    m = m > 0.f ? m : 1.0f;
    if (tid == 0) g_w2s[row] = m;
    float inv = 127.0f / m;
    uint32_t p1 = 0, p2 = 0;
#pragma unroll
    for (int j = 0; j < 4; j++) {
        int q1, q2; quant2(f[j], inv, q1, q2);
        p1 |= (uint32_t)(q1 & 255) << (j*8);
        p2 |= (uint32_t)(q2 & 255) << (j*8);
    }
    ((uint32_t*)g_w2i1)[(size_t)row*(I1/4) + tid] = p1;
    ((uint32_t*)g_w2i2)[(size_t)row*(I1/4) + tid] = p2;
}

__global__ __launch_bounds__(256) void quant_x(const float* __restrict__ x, int TP) {
    __shared__ float sred[8];
    int p = blockIdx.x; if (p >= TP) return;
    int tid = threadIdx.x;
    int tok = g_pair_tok[p];
    const float4* src = (const float4*)(x + (size_t)tok * H);
    float4 a = src[tid*2], b = src[tid*2+1];
    float f[8] = {a.x,a.y,a.z,a.w,b.x,b.y,b.z,b.w};
    float mv = 0.f;
#pragma unroll
    for (int j = 0; j < 8; j++) mv = fmaxf(mv, fabsf(f[j]));
    float m = blockmax8(mv, sred);
    m = m > 0.f ? m : 1.0f;
    if (tid == 0) g_xs[p] = m;
    float inv = 127.0f / m;
    uint32_t p1[2] = {0,0}, p2[2] = {0,0};
#pragma unroll
    for (int j = 0; j < 8; j++) {
        int q1, q2; quant2(f[j], inv, q1, q2);
        p1[j>>2] |= (uint32_t)(q1 & 255) << ((j&3)*8);
        p2[j>>2] |= (uint32_t)(q2 & 255) << ((j&3)*8);
    }
    ((uint2*)g_xi1)[(size_t)p*(H/8) + tid] = make_uint2(p1[0], p1[1]);
    ((uint2*)g_xi2)[(size_t)p*(H/8) + tid] = make_uint2(p2[0], p2[1]);
}

__global__ __launch_bounds__(256) void quant_h(int TP) {
    __shared__ float sred[8];
    int p = blockIdx.x; if (p >= TP) return;
    int tid = threadIdx.x;
    const float4* src = (const float4*)(g_h + (size_t)p * I1);
    float4 a = src[tid];
    float f[4] = {a.x,a.y,a.z,a.w};
    float mv = fmaxf(fmaxf(fabsf(f[0]), fabsf(f[1])), fmaxf(fabsf(f[2]), fabsf(f[3])));
    float m = blockmax8(mv, sred);
    m = m > 0.f ? m : 1.0f;
    if (tid == 0) g_hs[p] = m;
    float inv = 127.0f / m;
    uint32_t p1 = 0, p2 = 0;
#pragma unroll
    for (int j = 0; j < 4; j++) {
        int q1, q2; quant2(f[j], inv, q1, q2);
        p1 |= (uint32_t)(q1 & 255) << (j*8);
        p2 |= (uint32_t)(q2 & 255) << (j*8);
    }
    ((uint32_t*)g_hi1)[(size_t)p*(I1/4) + tid] = p1;
    ((uint32_t*)g_hi2)[(size_t)p*(I1/4) + tid] = p2;
}

// ---------------- grouped GEMM building blocks (int8, small warp tile) ----------------
// fill one 48KB stage: Ai1|Ai2 (128x128B) + Bi1|Bi2 (64x128B), SW128
__device__ __forceinline__ void stage_i8(uint32_t dst,
    const uint4* __restrict__ a1, const uint4* __restrict__ a2, int ars,
    const uint4* __restrict__ b1, const uint4* __restrict__ b2, int brs,
    int kc, int tid)
{
    int r0 = tid >> 3, c = tid & 7;
    int k8 = kc * 8;
#pragma unroll
    for (int p = 0; p < 4; p++) {
        int r = r0 + p * 32;
        uint32_t d = swz((uint32_t)(r * 128 + c * 16));
        size_t aoff = (size_t)r * ars + (k8 + c);
        cp16(dst +       d, a1 + aoff);
        cp16(dst + A_T + d, a2 + aoff);
    }
#pragma unroll
    for (int p = 0; p < 2; p++) {
        int r = r0 + p * 32;
        uint32_t d = swz((uint32_t)(r * 128 + c * 16));
        size_t boff = (size_t)r * brs + (k8 + c);
        cp16(dst + 2*A_T +       d, b1 + boff);
        cp16(dst + 2*A_T + B_T + d, b2 + boff);
    }
}

// one K=128 stage: 4 k32 steps, 3 int8 MMA terms, warp tile 32x32 (mt=2, nt=4)
__device__ __forceinline__ void compute_i8(uint32_t sbuf,
    int accM[2][4][4], int accC[2][4][4],
    int arow, int brow, int kA, int kB, uint32_t kxor)
{
    uint32_t a1b = sbuf, a2b = sbuf + A_T;
    uint32_t b1b = sbuf + 2*A_T, b2b = sbuf + 2*A_T + B_T;
#pragma unroll
    for (int ks = 0; ks < 4; ks++) {
        uint32_t A1[2][4], A2[2][4], B1[2][4], B2[2][4];
#pragma unroll
        for (int mt = 0; mt < 2; mt++) {
            int row = arow + mt * 16;
            uint32_t off = (uint32_t)(row * 128) + (((uint32_t)(ks*32 + kA)) ^ kxor);
            ldm_x4(A1[mt], a1b + off);
            ldm_x4(A2[mt], a2b + off);
        }
#pragma unroll
        for (int np = 0; np < 2; np++) {
            int row = brow + np * 16;
            uint32_t off = (uint32_t)(row * 128) + (((uint32_t)(ks*32 + kB)) ^ kxor);
            ldm_x4(B1[np], b1b + off);
            ldm_x4(B2[np], b2b + off);
        }
#pragma unroll
        for (int mt = 0; mt < 2; mt++) {
#pragma unroll
            for (int nt = 0; nt < 4; nt++) {
                const uint32_t* bj1 = &B1[nt >> 1][(nt & 1) * 2];
                const uint32_t* bj2 = &B2[nt >> 1][(nt & 1) * 2];
                mma_s8(accM[mt][nt], A1[mt], bj1[0], bj1[1]);   // i1*j1
                mma_s8(accC[mt][nt], A1[mt], bj2[0], bj2[1]);   // i1*j2
                mma_s8(accC[mt][nt], A2[mt], bj1[0], bj1[1]);   // i2*j1
            }
        }
    }
}

// ---------------- persistent fill cursor ----------------
struct FillCur {
    int w;
    int kc;
    const uint4 *a1, *a2, *b1, *b2;
};

template<int LAYER>
__device__ __forceinline__ void fill_load(FillCur& f, int nw) {
    if (f.w >= nw) return;
    int tile = f.w >> 5, ny = f.w & (NX - 1);
    int e  = g_tile_expert[tile];
    int pb = g_tile_pairbase[tile];
    int nb = ny * TNN;
    if (LAYER == 0) {
        f.a1 = g_xi1 + (size_t)pb*(H/16);
        f.a2 = g_xi2 + (size_t)pb*(H/16);
        f.b1 = g_w1i1 + ((size_t)e*I2 + nb)*(H/16);
        f.b2 = g_w1i2 + ((size_t)e*I2 + nb)*(H/16);
    } else {
        f.a1 = g_hi1 + (size_t)pb*(I1/16);
        f.a2 = g_hi2 + (size_t)pb*(I1/16);
        f.b1 = g_w2i1 + ((size_t)e*H + nb)*(I1/16);
        f.b2 = g_w2i2 + ((size_t)e*H + nb)*(I1/16);
    }
}

template<int LAYER>
__device__ __forceinline__ int fill_advance(FillCur& f, int nw, int nkc, int krs,
                                            uint32_t tb, int& buf_fill, int tid) {
    if (f.w >= nw) return 0;
    stage_i8(tb + buf_fill*STAGE_BYTES, f.a1, f.a2, krs, f.b1, f.b2, krs, f.kc, tid);
    CP_COMMIT();
    buf_fill = (buf_fill + 1 == NSTAGE) ? 0 : buf_fill + 1;
    if (++f.kc == nkc) { f.kc = 0; f.w += PGRID; fill_load<LAYER>(f, nw); }
    return 1;
}

// ---------------- fc1: persistent X @ W1^T (+b1) -> swiglu -> fp32 h ----------------
__global__ void __launch_bounds__(256, 1)
fc1_mma(const float* __restrict__ b1) {
    extern __shared__ __align__(1024) char smem[];
    uint32_t tb = smem_u32(smem);
    int tid = threadIdx.x;
    const int nw = g_n_tiles * NX;
    const int nkc = H / KCB, krs = H / 16;

    int lane = tid & 31, wid = tid >> 5;
    int warp_m = wid >> 1, warp_n = wid & 1;     // 4 x 2 warps, 32x32 each
    int g = lane >> 3, rowin = lane & 7;
    int arow = warp_m * 32 + (g & 1) * 8 + rowin;
    int brow = warp_n * 32 + (g >> 1) * 8 + rowin;
    int kA = (g >> 1) * 16, kB = (g & 1) * 16;
    uint32_t kxor = (uint32_t)rowin << 4;

    FillCur f; f.w = blockIdx.x; f.kc = 0;
    fill_load<0>(f, nw);
    int buf_fill = 0, buf_comp = 0, pend = 0;
    pend += fill_advance<0>(f, nw, nkc, krs, tb, buf_fill, tid);
    pend += fill_advance<0>(f, nw, nkc, krs, tb, buf_fill, tid);

    for (int w = blockIdx.x; w < nw; w += PGRID) {
        int tile = w >> 5, ny = w & (NX - 1);
        int e = g_tile_expert[tile];
        int pair_base = g_tile_pairbase[tile];
        int rows = g_counts[e] - g_tile_rowbase[tile]; if (rows > TMM) rows = TMM;
        int nbase = ny * TNN;

        int accM[2][4][4], accC[2][4][4];
#pragma unroll
        for (int a = 0; a < 2; a++)
#pragma unroll
            for (int b = 0; b < 4; b++)
#pragma unroll
                for (int c = 0; c < 4; c++) { accM[a][b][c] = 0; accC[a][b][c] = 0; }

        for (int kc = 0; kc < nkc; kc++) {
            if (pend >= 2) { CP_WAIT(1); pend = 1; }
            else           { CP_WAIT(0); pend = 0; }
            __syncthreads();
            compute_i8(tb + buf_comp*STAGE_BYTES, accM, accC, arow, brow, kA, kB, kxor);
            buf_comp = (buf_comp + 1 == NSTAGE) ? 0 : buf_comp + 1;
            pend += fill_advance<0>(f, nw, nkc, krs, tb, buf_fill, tid);
        }

        const float* b1e = b1 + (size_t)e*I2 + nbase;
        const float* w1s = g_w1s + (size_t)e*I2 + nbase;
#pragma unroll
        for (int mt = 0; mt < 2; mt++) {
#pragma unroll
            for (int hf = 0; hf < 2; hf++) {
                int row = warp_m*32 + mt*16 + (lane >> 2) + hf*8;
                if (row >= rows) continue;
                int pair = pair_base + row;
                float sx = g_xs[pair] * (1.0f / 16129.0f);
                float* hrow = g_h + (size_t)pair * I1 + (nbase >> 1);
#pragma unroll
                for (int nt = 0; nt < 4; nt++) {
                    int n = warp_n*32 + nt*8 + (lane & 3)*2;
                    float zg = sx * w1s[n]   * ((float)accM[mt][nt][hf*2]   + (float)accC[mt][nt][hf*2]   * (1.0f/254.0f)) + b1e[n];
                    float zl = sx * w1s[n+1] * ((float)accM[mt][nt][hf*2+1] + (float)accC[mt][nt][hf*2+1] * (1.0f/254.0f)) + b1e[n+1];
                    zg = fminf(zg, 7.0f);
                    zl = fminf(fmaxf(zl, -7.0f), 7.0f);
                    float hv = zg * (1.0f/(1.0f + __expf(-1.702f*zg))) * (zl + 1.0f);
                    hrow[n >> 1] = hv;
                }
            }
        }
    }
}

// ---------------- fc2: persistent h @ W2^T (+b2), gate-scaled atomic scatter ----------------
__global__ void __launch_bounds__(256, 1)
fc2_mma(const float* __restrict__ b2, float* __restrict__ out) {
    extern __shared__ __align__(1024) char smem[];
    uint32_t tb = smem_u32(smem);
    int tid = threadIdx.x;
    const int nw = g_n_tiles * NX;
    const int nkc = I1 / KCB, krs = I1 / 16;

    int lane = tid & 31, wid = tid >> 5;
    int warp_m = wid >> 1, warp_n = wid & 1;
    int g = lane >> 3, rowin = lane & 7;
    int arow = warp_m * 32 + (g & 1) * 8 + rowin;
    int brow = warp_n * 32 + (g >> 1) * 8 + rowin;
    int kA = (g >> 1) * 16, kB = (g & 1) * 16;
    uint32_t kxor = (uint32_t)rowin << 4;

    FillCur f; f.w = blockIdx.x; f.kc = 0;
    fill_load<1>(f, nw);
    int buf_fill = 0, buf_comp = 0, pend = 0;
    pend += fill_advance<1>(f, nw, nkc, krs, tb, buf_fill, tid);
    pend += fill_advance<1>(f, nw, nkc, krs, tb, buf_fill, tid);

    for (int w = blockIdx.x; w < nw; w += PGRID) {
        int tile = w >> 5, ny = w & (NX - 1);
        int e = g_tile_expert[tile];
        int pair_base = g_tile_pairbase[tile];
        int rows = g_counts[e] - g_tile_rowbase[tile]; if (rows > TMM) rows = TMM;
        int nbase = ny * TNN;

        int accM[2][4][4], accC[2][4][4];
#pragma unroll
        for (int a = 0; a < 2; a++)
#pragma unroll
            for (int b = 0; b < 4; b++)
#pragma unroll
                for (int c = 0; c < 4; c++) { accM[a][b][c] = 0; accC[a][b][c] = 0; }

        for (int kc = 0; kc < nkc; kc++) {
            if (pend >= 2) { CP_WAIT(1); pend = 1; }
            else           { CP_WAIT(0); pend = 0; }
            __syncthreads();
            compute_i8(tb + buf_comp*STAGE_BYTES, accM, accC, arow, brow, kA, kB, kxor);
            buf_comp = (buf_comp + 1 == NSTAGE) ? 0 : buf_comp + 1;
            pend += fill_advance<1>(f, nw, nkc, krs, tb, buf_fill, tid);
        }

        const float* b2e = b2 + (size_t)e*H + nbase;
        const float* w2s = g_w2s + (size_t)e*H + nbase;
#pragma unroll
        for (int mt = 0; mt < 2; mt++) {
#pragma unroll
            for (int hf = 0; hf < 2; hf++) {
                int row = warp_m*32 + mt*16 + (lane >> 2) + hf*8;
                if (row >= rows) continue;
                int pair = pair_base + row;
                int tok = g_pair_tok[pair];
                float gate = g_pair_gate[pair];
                float sh = g_hs[pair] * (1.0f / 16129.0f);
                float* orow = out + (size_t)tok*H + nbase;
#pragma unroll
                for (int nt = 0; nt < 4; nt++) {
                    int n = warp_n*32 + nt*8 + (lane & 3)*2;
                    float y0 = sh * w2s[n]   * ((float)accM[mt][nt][hf*2]   + (float)accC[mt][nt][hf*2]   * (1.0f/254.0f)) + b2e[n];
                    float y1 = sh * w2s[n+1] * ((float)accM[mt][nt][hf*2+1] + (float)accC[mt][nt][hf*2+1] * (1.0f/254.0f)) + b2e[n+1];
                    atomicAdd(orow + n,     gate * y0);
                    atomicAdd(orow + n + 1, gate * y1);
                }
            }
        }
    }
}

// ---------------- launch ----------------
extern "C" void kernel_launch(void* const* d_in, const int* in_sizes, int n_in,
                              void* d_out, int out_size) {
    const float* x  = (const float*)d_in[0];
    const float* gw = (const float*)d_in[1];
    const float* gb = (const float*)d_in[2];
    const float* w1 = (const float*)d_in[3];
    const float* b1 = (const float*)d_in[4];
    const float* w2 = (const float*)d_in[5];
    const float* b2 = (const float*)d_in[6];
    float* out = (float*)d_out;
    int T = in_sizes[0] / H;   // 8192

    cudaFuncSetAttribute(fc1_mma, cudaFuncAttributeMaxDynamicSharedMemorySize, SMEM_DYN);
    cudaFuncSetAttribute(fc2_mma, cudaFuncAttributeMaxDynamicSharedMemorySize, SMEM_DYN);

    cudaMemsetAsync(d_out, 0, (size_t)out_size * sizeof(float));
    init_kernel<<<1, 64>>>();
    router_gemm<<<T / 32, 256>>>(x, gw, gb);
    topk_kernel<<<(T + 7) / 8, 256>>>(T);
    scan_kernel<<<1, 32>>>();
    scatter_kernel<<<(T + 255) / 256, 256>>>(T);

    quant_w1<<<E * I2, 256>>>(w1);
    quant_w2<<<E * H, 256>>>(w2);
    quant_x<<<2 * T, 256>>>(x, 2 * T);

    fc1_mma<<<PGRID, 256, SMEM_DYN>>>(b1);
    quant_h<<<2 * T, 256>>>(2 * T);
    fc2_mma<<<PGRID, 256, SMEM_DYN>>>(b2, out);
}

// round 17
// speedup vs baseline: 4.4485x; 4.4485x over previous
#include <cuda_runtime.h>
#include <cuda_bf16.h>
#include <cstdint>

#define H   2048
#define I1  1024
#define I2  2048
#define E   32
#define MAXT 8192
#define MAXPAIR (2*MAXT)
#define MAXPAIRP (MAXPAIR + 128)
#define MAXTILES 160
#define TMM 128          // CTA M tile
#define TNN 128          // CTA N tile
#define NX  16           // N-chunks per layer (I2/TNN == H/TNN == 16)
#define KC  64           // K chunk = 64 elems per stage
#define TILE_A 16384     // one 128x64 bf16 A tile (hi or lo)
#define BROW 288         // padded fp32 B row stride in bytes (256 data + 32 pad)
#define B_STAGE (128*BROW)                 /* 36864 */
#define STAGE_BYTES (2*TILE_A + B_STAGE)   /* 69632 */
#define NSTAGE 3
#define SMEM_DYN (NSTAGE*STAGE_BYTES)      /* 208896 */
#define PGRID 152        // persistent grid (GB300 = 152 SMs)

// ---------------- device scratch ----------------
__device__ uint4 g_xhi4[(size_t)MAXPAIRP*(H/8)];
__device__ uint4 g_xlo4[(size_t)MAXPAIRP*(H/8)];
__device__ uint4 g_hhi4[(size_t)MAXPAIRP*(I1/8)];
__device__ uint4 g_hlo4[(size_t)MAXPAIRP*(I1/8)];

__device__ int   g_counts[E];
__device__ int   g_cursor[E];
__device__ int   g_offsets[E];
__device__ int   g_tok_e[MAXT * 2];
__device__ float g_tok_g[MAXT * 2];
__device__ int   g_pair_tok[MAXPAIR];
__device__ float g_pair_gate[MAXPAIR];
__device__ int   g_tile_expert[MAXTILES];
__device__ int   g_tile_rowbase[MAXTILES];
__device__ int   g_tile_pairbase[MAXTILES];
__device__ int   g_n_tiles;

// ---------------- PTX helpers (plain-sm_103-legal) ----------------
__device__ __forceinline__ uint32_t smem_u32(const void* p) {
    uint32_t a;
    asm("{ .reg .u64 t; cvta.to.shared.u64 t, %1; cvt.u32.u64 %0, t; }" : "=r"(a) : "l"(p));
    return a;
}
__device__ __forceinline__ void cp16(uint32_t s, const void* g) {
    asm volatile("cp.async.cg.shared.global [%0], [%1], 16;" :: "r"(s), "l"(g));
}
#define CP_COMMIT() asm volatile("cp.async.commit_group;" ::: "memory")
#define CP_WAIT(n)  asm volatile("cp.async.wait_group %0;" :: "n"(n) : "memory")

__device__ __forceinline__ void ldm_x4(uint32_t r[4], uint32_t addr) {
    asm volatile("ldmatrix.sync.aligned.m8n8.x4.shared.b16 {%0,%1,%2,%3}, [%4];"
        : "=r"(r[0]), "=r"(r[1]), "=r"(r[2]), "=r"(r[3]) : "r"(addr));
}
__device__ __forceinline__ void mma16816(float c[4], const uint32_t a[4],
                                         uint32_t b0, uint32_t b1) {
    asm volatile("mma.sync.aligned.m16n8k16.row.col.f32.bf16.bf16.f32 "
        "{%0,%1,%2,%3}, {%4,%5,%6,%7}, {%8,%9}, {%0,%1,%2,%3};"
        : "+f"(c[0]), "+f"(c[1]), "+f"(c[2]), "+f"(c[3])
        : "r"(a[0]), "r"(a[1]), "r"(a[2]), "r"(a[3]), "r"(b0), "r"(b1));
}
__device__ __forceinline__ void lds64f(float2& v, uint32_t a) {
    asm volatile("ld.shared.v2.f32 {%0,%1}, [%2];" : "=f"(v.x), "=f"(v.y) : "r"(a));
}
// pack (v.x -> low half, v.y -> high half) with rn; residual pack for lo term
__device__ __forceinline__ void pack_hilo(const float2& v, uint32_t& bh, uint32_t& bl) {
    asm("cvt.rn.bf16x2.f32 %0, %1, %2;" : "=r"(bh) : "f"(v.y), "f"(v.x));
    float hx = __uint_as_float(bh << 16);
    float hy = __uint_as_float(bh & 0xffff0000u);
    asm("cvt.rn.bf16x2.f32 %0, %1, %2;" : "=r"(bl) : "f"(v.y - hy), "f"(v.x - hx));
}
__device__ __forceinline__ uint32_t swz(uint32_t x) { return x ^ ((x >> 3) & 0x70); }

__device__ __forceinline__ void split8(const float4& a, const float4& b, uint4& hi, uint4& lo) {
    float f[8] = {a.x, a.y, a.z, a.w, b.x, b.y, b.z, b.w};
    unsigned v[8], w[8];
#pragma unroll
    for (int j = 0; j < 8; j++) {
        __nv_bfloat16 x = __float2bfloat16(f[j]);
        v[j] = (unsigned)__bfloat16_as_ushort(x);
        w[j] = (unsigned)__bfloat16_as_ushort(__float2bfloat16(f[j] - __bfloat162float(x)));
    }
    hi = make_uint4(v[0]|(v[1]<<16), v[2]|(v[3]<<16), v[4]|(v[5]<<16), v[6]|(v[7]<<16));
    lo = make_uint4(w[0]|(w[1]<<16), w[2]|(w[3]<<16), w[4]|(w[5]<<16), w[6]|(w[7]<<16));
}

// ---------------- routing kernels ----------------
__global__ void init_kernel() {
    int i = threadIdx.x;
    if (i < E) { g_counts[i] = 0; g_cursor[i] = 0; }
    if (i == 0) g_n_tiles = 0;
}

// fused router GEMM + softmax + top-2 (no logits round-trip, no extra launch)
__global__ __launch_bounds__(256) void router_topk(const float* __restrict__ x,
                                                   const float* __restrict__ gw,
                                                   const float* __restrict__ gb) {
    __shared__ __align__(16) float xs[32][36];
    __shared__ __align__(16) float ws[32][36];
    int tid = threadIdx.x;
    int tx = tid & 7, ty = tid >> 3;
    int tbase = blockIdx.x * 32;
    int lrow = tid >> 3, lk4 = (tid & 7) * 4;
    float acc[4] = {0.f, 0.f, 0.f, 0.f};
    const float* xp = x  + (size_t)(tbase + lrow) * H + lk4;
    const float* wp = gw + (size_t)lrow * H + lk4;
    for (int kb = 0; kb < H; kb += 32) {
        float4 xv = *(const float4*)(xp + kb);
        float4 wv = *(const float4*)(wp + kb);
        *(float4*)&xs[lrow][lk4] = xv;
        ws[lk4+0][lrow] = wv.x; ws[lk4+1][lrow] = wv.y;
        ws[lk4+2][lrow] = wv.z; ws[lk4+3][lrow] = wv.w;
        __syncthreads();
#pragma unroll
        for (int k = 0; k < 32; ++k) {
            float xv1 = xs[ty][k];
            float4 w4 = *(const float4*)&ws[k][tx*4];
            acc[0] = fmaf(xv1, w4.x, acc[0]); acc[1] = fmaf(xv1, w4.y, acc[1]);
            acc[2] = fmaf(xv1, w4.z, acc[2]); acc[3] = fmaf(xv1, w4.w, acc[3]);
        }
        __syncthreads();
    }
    // stage logits in ws[token][expert] (loop's trailing sync makes this safe)
#pragma unroll
    for (int j = 0; j < 4; ++j) ws[ty][tx*4 + j] = acc[j] + gb[tx*4 + j];
    __syncthreads();

    if (tid < 32) {
        int t = tbase + tid;
        float p[E];
        float m = ws[tid][0];
#pragma unroll
        for (int e = 1; e < E; ++e) m = fmaxf(m, ws[tid][e]);
        float s = 0.f;
#pragma unroll
        for (int e = 0; e < E; ++e) { p[e] = __expf(ws[tid][e] - m); s += p[e]; }
        float inv = 1.0f / s;
        float v0 = -1.0f; int e0 = 0;
#pragma unroll
        for (int e = 0; e < E; ++e) { float pe = p[e] * inv; p[e] = pe;
            if (pe > v0) { v0 = pe; e0 = e; } }
        float v1 = -1.0f; int e1 = 0;
#pragma unroll
        for (int e = 0; e < E; ++e)
            if (e != e0 && p[e] > v1) { v1 = p[e]; e1 = e; }
        g_tok_e[t*2+0] = e0; g_tok_g[t*2+0] = v0;
        g_tok_e[t*2+1] = e1; g_tok_g[t*2+1] = v1;
        atomicAdd(&g_counts[e0], 1);
        atomicAdd(&g_counts[e1], 1);
    }
}

__global__ void scan_kernel() {
    if (threadIdx.x != 0) return;
    int off = 0, nt = 0;
    for (int e = 0; e < E; ++e) {
        g_offsets[e] = off;
        int c = g_counts[e];
        for (int rb = 0; rb < c; rb += TMM) {
            g_tile_expert[nt] = e; g_tile_rowbase[nt] = rb; g_tile_pairbase[nt] = off + rb;
            nt++;
        }
        off += c;
    }
    g_n_tiles = nt;
}

__global__ void scatter_kernel(int T) {
    int t = blockIdx.x * blockDim.x + threadIdx.x;
    if (t >= T) return;
#pragma unroll
    for (int j = 0; j < 2; ++j) {
        int e = g_tok_e[t*2+j];
        int pos = g_offsets[e] + atomicAdd(&g_cursor[e], 1);
        g_pair_tok[pos]  = t;
        g_pair_gate[pos] = g_tok_g[t*2+j];
    }
}

// ---------------- gather (x split only; weights stay fp32) ----------------
__global__ __launch_bounds__(256) void gather_x(const float* __restrict__ x) {
    int p = blockIdx.x, tid = threadIdx.x;
    int tok = g_pair_tok[p];
    const float4* src = (const float4*)(x + (size_t)tok * H);
    uint4 hi, lo; split8(src[tid*2], src[tid*2+1], hi, lo);
    g_xhi4[(size_t)p*(H/8) + tid] = hi;
    g_xlo4[(size_t)p*(H/8) + tid] = lo;
}

// ---------------- grouped GEMM building blocks ----------------
// fill one 68KB stage: Ahi|Alo (128 rows x 128B, SW128) + B fp32 (128 rows x 256B, 288B stride)
__device__ __forceinline__ void stage_fc(uint32_t dst,
    const uint4* __restrict__ ahi, const uint4* __restrict__ alo, int ars,
    const float* __restrict__ bsrc, int brs, int kc, int tid)
{
    int r0 = tid >> 3, c = tid & 7;
    int k8 = kc * 8;
#pragma unroll
    for (int p = 0; p < 4; p++) {
        int r = r0 + p * 32;
        uint32_t d = swz((uint32_t)(r * 128 + c * 16));
        size_t aoff = (size_t)r * ars + (k8 + c);
        cp16(dst +          d, ahi + aoff);
        cp16(dst + TILE_A + d, alo + aoff);
    }
    uint32_t bb = dst + 2*TILE_A;
    int k0 = kc * KC;
#pragma unroll
    for (int t = 0; t < 8; t++) {
        int cid = tid + t * 256;
        int r = cid >> 4, c16 = cid & 15;
        cp16(bb + (uint32_t)(r * BROW + c16 * 16),
             bsrc + (size_t)r * brs + k0 + c16 * 4);
    }
}

// one KC=64 stage: 4 k16 steps; A via ldmatrix (pre-split), B converted from fp32 in regs
// (R14 scheduling: per-nt convert + MMA group — empirically best)
__device__ __forceinline__ void compute_stage(uint32_t sbuf, float acc[4][4][4],
                                              int arow, int kA, uint32_t kxor,
                                              uint32_t boff_lane)
{
    uint32_t ab = sbuf, bb = sbuf + 2*TILE_A;
#pragma unroll
    for (int ks = 0; ks < 4; ks++) {
        uint32_t Ah[4][4], Al[4][4];
#pragma unroll
        for (int mt = 0; mt < 4; mt++) {
            int row = arow + mt * 16;
            uint32_t off = (uint32_t)(row * 128) + (((uint32_t)(ks*32 + kA)) ^ kxor);
            ldm_x4(Ah[mt], ab + off);
            ldm_x4(Al[mt], ab + TILE_A + off);
        }
#pragma unroll
        for (int nt = 0; nt < 4; nt++) {
            uint32_t a0 = bb + boff_lane + (uint32_t)(nt * 8 * BROW + ks * 64);
            float2 v0, v1;
            lds64f(v0, a0);
            lds64f(v1, a0 + 32);
            uint32_t bh0, bl0, bh1, bl1;
            pack_hilo(v0, bh0, bl0);
            pack_hilo(v1, bh1, bl1);
#pragma unroll
            for (int mt = 0; mt < 4; mt++) {
                mma16816(acc[mt][nt], Ah[mt], bh0, bh1);   // hi*hi
                mma16816(acc[mt][nt], Ah[mt], bl0, bl1);   // hi*lo
                mma16816(acc[mt][nt], Al[mt], bh0, bh1);   // lo*hi
            }
        }
    }
}

// ---------------- persistent fill cursor ----------------
struct FillCur {
    int w;       // global work id (w = tile*NX + ny); invalid when >= nw
    int kc;      // next k-chunk to fill within work w
    const uint4 *ah, *al;
    const float *b;
};

// layer=0: fc1 (A=x, B=w1 fp32, K=H)  layer=1: fc2 (A=h, B=w2 fp32, K=I1)
template<int LAYER>
__device__ __forceinline__ void fill_load(FillCur& f, int nw,
                                          const float* w1, const float* w2) {
    if (f.w >= nw) return;
    int tile = f.w >> 4, ny = f.w & (NX - 1);
    int e  = g_tile_expert[tile];
    int pb = g_tile_pairbase[tile];
    int nb = ny * TNN;
    if (LAYER == 0) {
        f.ah = g_xhi4 + (size_t)pb*(H/8);
        f.al = g_xlo4 + (size_t)pb*(H/8);
        f.b  = w1 + ((size_t)e*I2 + nb)*H;
    } else {
        f.ah = g_hhi4 + (size_t)pb*(I1/8);
        f.al = g_hlo4 + (size_t)pb*(I1/8);
        f.b  = w2 + ((size_t)e*H + nb)*I1;
    }
}

template<int LAYER>
__device__ __forceinline__ int fill_advance(FillCur& f, int nw, int nkc,
                                            int ars, int brs,
                                            const float* w1, const float* w2,
                                            uint32_t tb, int& buf_fill, int tid) {
    if (f.w >= nw) return 0;
    stage_fc(tb + buf_fill*STAGE_BYTES, f.ah, f.al, ars, f.b, brs, f.kc, tid);
    CP_COMMIT();
    buf_fill = (buf_fill + 1 == NSTAGE) ? 0 : buf_fill + 1;
    if (++f.kc == nkc) { f.kc = 0; f.w += PGRID; fill_load<LAYER>(f, nw, w1, w2); }
    return 1;
}

// ---------------- fc1: persistent X @ W1^T (+b1) -> swiglu -> split-bf16 h ----------------
__global__ void __launch_bounds__(256, 1)
fc1_mma(const float* __restrict__ w1, const float* __restrict__ b1) {
    extern __shared__ __align__(1024) char smem[];
    uint32_t tb = smem_u32(smem);
    int tid = threadIdx.x;
    const int nw = g_n_tiles * NX;
    const int nkc = H / KC, ars = H / 8, brs = H;

    int lane = tid & 31, wid = tid >> 5;
    int warp_m = wid >> 2, warp_n = wid & 3;
    int g = lane >> 3, rowin = lane & 7;
    int arow = warp_m * 64 + (g & 1) * 8 + rowin;
    int kA = (g >> 1) * 16;
    uint32_t kxor = (uint32_t)rowin << 4;
    uint32_t boff_lane = (uint32_t)((warp_n*32 + (lane >> 2)) * BROW + (lane & 3) * 8);

    FillCur f; f.w = blockIdx.x; f.kc = 0;
    fill_load<0>(f, nw, w1, nullptr);
    int buf_fill = 0, buf_comp = 0, pend = 0;
    pend += fill_advance<0>(f, nw, nkc, ars, brs, w1, nullptr, tb, buf_fill, tid);
    pend += fill_advance<0>(f, nw, nkc, ars, brs, w1, nullptr, tb, buf_fill, tid);

    for (int w = blockIdx.x; w < nw; w += PGRID) {
        int tile = w >> 4, ny = w & (NX - 1);
        int e = g_tile_expert[tile];
        int pair_base = g_tile_pairbase[tile];
        int rows = g_counts[e] - g_tile_rowbase[tile]; if (rows > TMM) rows = TMM;
        int nbase = ny * TNN;

        float acc[4][4][4];
#pragma unroll
        for (int a = 0; a < 4; a++)
#pragma unroll
            for (int b = 0; b < 4; b++)
#pragma unroll
                for (int c = 0; c < 4; c++) acc[a][b][c] = 0.f;

        for (int kc = 0; kc < nkc; kc++) {
            if (pend >= 2) { CP_WAIT(1); pend = 1; }
            else           { CP_WAIT(0); pend = 0; }
            __syncthreads();
            compute_stage(tb + buf_comp*STAGE_BYTES, acc, arow, kA, kxor, boff_lane);
            buf_comp = (buf_comp + 1 == NSTAGE) ? 0 : buf_comp + 1;
            pend += fill_advance<0>(f, nw, nkc, ars, brs, w1, nullptr, tb, buf_fill, tid);
        }

        // epilogue (overlaps the in-flight fills for the next work item)
        const float* b1e = b1 + (size_t)e*I2 + nbase;
        __nv_bfloat16* hhB = (__nv_bfloat16*)g_hhi4;
        __nv_bfloat16* hlB = (__nv_bfloat16*)g_hlo4;
#pragma unroll
        for (int mt = 0; mt < 4; mt++) {
#pragma unroll
            for (int hf = 0; hf < 2; hf++) {
                int row = warp_m*64 + mt*16 + (lane >> 2) + hf*8;
                if (row >= rows) continue;
                int pair = pair_base + row;
                size_t hbase = (size_t)pair * I1 + (nbase >> 1);
#pragma unroll
                for (int nt = 0; nt < 4; nt++) {
                    int n = warp_n*32 + nt*8 + (lane & 3)*2;
                    float zg = acc[mt][nt][hf*2]     + b1e[n];
                    float zl = acc[mt][nt][hf*2 + 1] + b1e[n + 1];
                    zg = fminf(zg, 7.0f);
                    zl = fminf(fmaxf(zl, -7.0f), 7.0f);
                    float hv = zg * (1.0f/(1.0f + __expf(-1.702f*zg))) * (zl + 1.0f);
                    __nv_bfloat16 hb = __float2bfloat16(hv);
                    hhB[hbase + (n >> 1)] = hb;
                    hlB[hbase + (n >> 1)] = __float2bfloat16(hv - __bfloat162float(hb));
                }
            }
        }
    }
}

// ---------------- fc2: persistent h @ W2^T (+b2), gate-scaled atomic scatter ----------------
__global__ void __launch_bounds__(256, 1)
fc2_mma(const float* __restrict__ w2, const float* __restrict__ b2,
        float* __restrict__ out) {
    extern __shared__ __align__(1024) char smem[];
    uint32_t tb = smem_u32(smem);
    int tid = threadIdx.x;
    const int nw = g_n_tiles * NX;
    const int nkc = I1 / KC, ars = I1 / 8, brs = I1;

    int lane = tid & 31, wid = tid >> 5;
    int warp_m = wid >> 2, warp_n = wid & 3;
    int g = lane >> 3, rowin = lane & 7;
    int arow = warp_m * 64 + (g & 1) * 8 + rowin;
    int kA = (g >> 1) * 16;
    uint32_t kxor = (uint32_t)rowin << 4;
    uint32_t boff_lane = (uint32_t)((warp_n*32 + (lane >> 2)) * BROW + (lane & 3) * 8);

    FillCur f; f.w = blockIdx.x; f.kc = 0;
    fill_load<1>(f, nw, nullptr, w2);
    int buf_fill = 0, buf_comp = 0, pend = 0;
    pend += fill_advance<1>(f, nw, nkc, ars, brs, nullptr, w2, tb, buf_fill, tid);
    pend += fill_advance<1>(f, nw, nkc, ars, brs, nullptr, w2, tb, buf_fill, tid);

    for (int w = blockIdx.x; w < nw; w += PGRID) {
        int tile = w >> 4, ny = w & (NX - 1);
        int e = g_tile_expert[tile];
        int pair_base = g_tile_pairbase[tile];
        int rows = g_counts[e] - g_tile_rowbase[tile]; if (rows > TMM) rows = TMM;
        int nbase = ny * TNN;

        float acc[4][4][4];
#pragma unroll
        for (int a = 0; a < 4; a++)
#pragma unroll
            for (int b = 0; b < 4; b++)
#pragma unroll
                for (int c = 0; c < 4; c++) acc[a][b][c] = 0.f;

        for (int kc = 0; kc < nkc; kc++) {
            if (pend >= 2) { CP_WAIT(1); pend = 1; }
            else           { CP_WAIT(0); pend = 0; }
            __syncthreads();
            compute_stage(tb + buf_comp*STAGE_BYTES, acc, arow, kA, kxor, boff_lane);
            buf_comp = (buf_comp + 1 == NSTAGE) ? 0 : buf_comp + 1;
            pend += fill_advance<1>(f, nw, nkc, ars, brs, nullptr, w2, tb, buf_fill, tid);
        }

        const float* b2e = b2 + (size_t)e*H + nbase;
#pragma unroll
        for (int mt = 0; mt < 4; mt++) {
#pragma unroll
            for (int hf = 0; hf < 2; hf++) {
                int row = warp_m*64 + mt*16 + (lane >> 2) + hf*8;
                if (row >= rows) continue;
                int pair = pair_base + row;
                int tok = g_pair_tok[pair];
                float gate = g_pair_gate[pair];
                float* orow = out + (size_t)tok*H + nbase;
#pragma unroll
                for (int nt = 0; nt < 4; nt++) {
                    int n = warp_n*32 + nt*8 + (lane & 3)*2;
                    float y0 = acc[mt][nt][hf*2]     + b2e[n];
                    float y1 = acc[mt][nt][hf*2 + 1] + b2e[n + 1];
                    atomicAdd(orow + n,     gate * y0);
                    atomicAdd(orow + n + 1, gate * y1);
                }
            }
        }
    }
}

// ---------------- launch ----------------
extern "C" void kernel_launch(void* const* d_in, const int* in_sizes, int n_in,
                              void* d_out, int out_size) {
    const float* x  = (const float*)d_in[0];
    const float* gw = (const float*)d_in[1];
    const float* gb = (const float*)d_in[2];
    const float* w1 = (const float*)d_in[3];
    const float* b1 = (const float*)d_in[4];
    const float* w2 = (const float*)d_in[5];
    const float* b2 = (const float*)d_in[6];
    float* out = (float*)d_out;
    int T = in_sizes[0] / H;   // 8192

    cudaFuncSetAttribute(fc1_mma, cudaFuncAttributeMaxDynamicSharedMemorySize, SMEM_DYN);
    cudaFuncSetAttribute(fc2_mma, cudaFuncAttributeMaxDynamicSharedMemorySize, SMEM_DYN);

    cudaMemsetAsync(d_out, 0, (size_t)out_size * sizeof(float));
    init_kernel<<<1, 64>>>();
    router_topk<<<T / 32, 256>>>(x, gw, gb);
    scan_kernel<<<1, 32>>>();
    scatter_kernel<<<(T + 255) / 256, 256>>>(T);
    gather_x<<<2 * T, 256>>>(x);

    fc1_mma<<<PGRID, 256, SMEM_DYN>>>(w1, b1);
    fc2_mma<<<PGRID, 256, SMEM_DYN>>>(w2, b2, out);
}